// round 1
// baseline (speedup 1.0000x reference)
#include <cuda_runtime.h>
#include <math.h>

#define HID 1024
#define NH 16
#define HD 64
#define BB 2
#define SS 2048
#define M_TOT (BB * SS)

// Scratch for Q/K/V in [B, H, S, D] layout (device globals: allocation-free).
__device__ float g_q[BB * NH * SS * HD];
__device__ float g_k[BB * NH * SS * HD];
__device__ float g_v[BB * NH * SS * HD];

// ---------------------------------------------------------------------------
// Fused QKV projection: X[4096,1024] @ W[1024,1024] + b, for W in {Wq,Wk,Wv}
// (blockIdx.z selects). 128x128x8 tiling, 8x8 micro-tile per thread.
// Output written directly in [B,H,S,D] layout.
// ---------------------------------------------------------------------------
__global__ __launch_bounds__(256) void qkv_gemm(
    const float* __restrict__ X,
    const float* __restrict__ Wq, const float* __restrict__ bq,
    const float* __restrict__ Wk, const float* __restrict__ bk,
    const float* __restrict__ Wv, const float* __restrict__ bv)
{
    const float* W;
    const float* bias;
    float* out;
    if (blockIdx.z == 0)      { W = Wq; bias = bq; out = g_q; }
    else if (blockIdx.z == 1) { W = Wk; bias = bk; out = g_k; }
    else                      { W = Wv; bias = bv; out = g_v; }

    __shared__ float As[8][128];   // A tile transposed: As[k][m]
    __shared__ float Bs[8][128];   // B tile: Bs[k][n]

    const int tid = threadIdx.x;
    const int m0 = blockIdx.y * 128;
    const int n0 = blockIdx.x * 128;

    // Global-load assignments
    const int lam = tid >> 1;            // 0..127 : row within A tile
    const int lak = (tid & 1) * 4;       // 0 or 4 : col group within A tile
    const int lbk = tid >> 5;            // 0..7   : row within B tile
    const int lbn = (tid & 31) * 4;      // 0..124 : col within B tile

    // Compute assignments (split 4+4 rows/cols for conflict-free LDS.128)
    const int tx = tid & 15;             // column group
    const int ty = tid >> 4;             // row group

    float c[8][8];
#pragma unroll
    for (int i = 0; i < 8; i++)
#pragma unroll
        for (int j = 0; j < 8; j++) c[i][j] = 0.f;

    for (int k0 = 0; k0 < HID; k0 += 8) {
        float4 av  = *(const float4*)(X + (m0 + lam) * HID + k0 + lak);
        float4 bv4 = *(const float4*)(W + (k0 + lbk) * HID + n0 + lbn);
        __syncthreads();
        As[lak + 0][lam] = av.x;
        As[lak + 1][lam] = av.y;
        As[lak + 2][lam] = av.z;
        As[lak + 3][lam] = av.w;
        *(float4*)&Bs[lbk][lbn] = bv4;
        __syncthreads();

#pragma unroll
        for (int kk = 0; kk < 8; kk++) {
            float a[8], b[8];
            *(float4*)&a[0] = *(const float4*)&As[kk][ty * 4];
            *(float4*)&a[4] = *(const float4*)&As[kk][ty * 4 + 64];
            *(float4*)&b[0] = *(const float4*)&Bs[kk][tx * 4];
            *(float4*)&b[4] = *(const float4*)&Bs[kk][tx * 4 + 64];
#pragma unroll
            for (int i = 0; i < 8; i++)
#pragma unroll
                for (int j = 0; j < 8; j++)
                    c[i][j] = fmaf(a[i], b[j], c[i][j]);
        }
    }

    // Epilogue: add bias, scatter into [B,H,S,D]
#pragma unroll
    for (int i = 0; i < 8; i++) {
        const int rloc = (i < 4) ? (ty * 4 + i) : (ty * 4 + 64 + (i - 4));
        const int gm = m0 + rloc;
        const int bsel = gm >> 11;          // / 2048
        const int srow = gm & (SS - 1);
#pragma unroll
        for (int jg = 0; jg < 2; jg++) {
            const int gn = n0 + tx * 4 + jg * 64;
            const int h = gn >> 6;
            const int d = gn & 63;
            float4 bb = *(const float4*)(bias + gn);
            float4 r;
            r.x = c[i][jg * 4 + 0] + bb.x;
            r.y = c[i][jg * 4 + 1] + bb.y;
            r.z = c[i][jg * 4 + 2] + bb.z;
            r.w = c[i][jg * 4 + 3] + bb.w;
            *(float4*)(out + (((size_t)(bsel * NH + h) * SS + srow) * HD) + d) = r;
        }
    }
}

// ---------------------------------------------------------------------------
// Flash attention (fp32): one thread = one query row. d=64 in registers.
// K/V tiles of 64 rows staged through SMEM. Online softmax.
// ---------------------------------------------------------------------------
__global__ __launch_bounds__(128) void attn_kernel(
    const float* __restrict__ mask, float* __restrict__ out)
{
    const int b = blockIdx.z;
    const int h = blockIdx.y;
    const int qrow = blockIdx.x * 128 + threadIdx.x;

    const float* qptr = g_q + ((size_t)(b * NH + h) * SS + qrow) * HD;
    float4 q[16], acc[16];
#pragma unroll
    for (int i = 0; i < 16; i++) {
        q[i] = *(const float4*)(qptr + i * 4);
        acc[i] = make_float4(0.f, 0.f, 0.f, 0.f);
    }

    float mrun = -INFINITY;
    float l = 0.f;

    __shared__ float ks[64 * HD];
    __shared__ float vs[64 * HD];
    __shared__ float msk[64];

    const float* kbase = g_k + (size_t)(b * NH + h) * SS * HD;
    const float* vbase = g_v + (size_t)(b * NH + h) * SS * HD;
    const float* mbase = mask + b * SS;
    const float NEGBIG = -3.4028234663852886e38f;  // finfo(float32).min

    for (int t = 0; t < SS / 64; t++) {
        __syncthreads();
        const float4* kg = (const float4*)(kbase + (size_t)t * 64 * HD);
        const float4* vg = (const float4*)(vbase + (size_t)t * 64 * HD);
#pragma unroll
        for (int i = 0; i < 8; i++) {
            int f = threadIdx.x + i * 128;
            ((float4*)ks)[f] = kg[f];
            ((float4*)vs)[f] = vg[f];
        }
        if (threadIdx.x < 64) msk[threadIdx.x] = mbase[t * 64 + threadIdx.x];
        __syncthreads();

        for (int j = 0; j < 64; j++) {
            const float4* kr = (const float4*)(ks + j * HD);
            float s0 = 0.f, s1 = 0.f, s2 = 0.f, s3 = 0.f;
#pragma unroll
            for (int i = 0; i < 16; i += 4) {
                float4 k0 = kr[i], k1 = kr[i + 1], k2 = kr[i + 2], k3 = kr[i + 3];
                s0 = fmaf(q[i].x,     k0.x, s0); s0 = fmaf(q[i].y,     k0.y, s0);
                s0 = fmaf(q[i].z,     k0.z, s0); s0 = fmaf(q[i].w,     k0.w, s0);
                s1 = fmaf(q[i + 1].x, k1.x, s1); s1 = fmaf(q[i + 1].y, k1.y, s1);
                s1 = fmaf(q[i + 1].z, k1.z, s1); s1 = fmaf(q[i + 1].w, k1.w, s1);
                s2 = fmaf(q[i + 2].x, k2.x, s2); s2 = fmaf(q[i + 2].y, k2.y, s2);
                s2 = fmaf(q[i + 2].z, k2.z, s2); s2 = fmaf(q[i + 2].w, k2.w, s2);
                s3 = fmaf(q[i + 3].x, k3.x, s3); s3 = fmaf(q[i + 3].y, k3.y, s3);
                s3 = fmaf(q[i + 3].z, k3.z, s3); s3 = fmaf(q[i + 3].w, k3.w, s3);
            }
            float s = (s0 + s1) + (s2 + s3);
            s = s * 0.125f + (1.0f - msk[j]) * NEGBIG;

            if (s > mrun) {           // rare rescale path (~ln(S) times/row)
                float corr = __expf(mrun - s);
                mrun = s;
                l *= corr;
#pragma unroll
                for (int i = 0; i < 16; i++) {
                    acc[i].x *= corr; acc[i].y *= corr;
                    acc[i].z *= corr; acc[i].w *= corr;
                }
            }
            float p = __expf(s - mrun);
            l += p;
            const float4* vr = (const float4*)(vs + j * HD);
#pragma unroll
            for (int i = 0; i < 16; i++) {
                float4 vv = vr[i];
                acc[i].x = fmaf(p, vv.x, acc[i].x);
                acc[i].y = fmaf(p, vv.y, acc[i].y);
                acc[i].z = fmaf(p, vv.z, acc[i].z);
                acc[i].w = fmaf(p, vv.w, acc[i].w);
            }
        }
    }

    const float inv = 1.0f / l;
    float* optr = out + ((size_t)(b * SS + qrow)) * HID + h * HD;
#pragma unroll
    for (int i = 0; i < 16; i++) {
        float4 r;
        r.x = acc[i].x * inv; r.y = acc[i].y * inv;
        r.z = acc[i].z * inv; r.w = acc[i].w * inv;
        *(float4*)(optr + i * 4) = r;
    }
}

// ---------------------------------------------------------------------------
extern "C" void kernel_launch(void* const* d_in, const int* in_sizes, int n_in,
                              void* d_out, int out_size)
{
    const float* X    = (const float*)d_in[0];  // hidden_states [2,2048,1024]
    const float* mask = (const float*)d_in[1];  // attention_mask [2,2048]
    const float* Wq   = (const float*)d_in[2];
    const float* bq   = (const float*)d_in[3];
    const float* Wk   = (const float*)d_in[4];
    const float* bk   = (const float*)d_in[5];
    const float* Wv   = (const float*)d_in[6];
    const float* bv   = (const float*)d_in[7];
    float* out = (float*)d_out;

    dim3 ggrid(HID / 128, M_TOT / 128, 3);   // (8, 32, 3)
    qkv_gemm<<<ggrid, 256>>>(X, Wq, bq, Wk, bk, Wv, bv);

    dim3 agrid(SS / 128, NH, BB);            // (16, 16, 2)
    attn_kernel<<<agrid, 128>>>(mask, out);
}